// round 1
// baseline (speedup 1.0000x reference)
#include <cuda_runtime.h>
#include <math.h>

#define BT    16384
#define DOBS  512
#define DD    128
#define NS    16
#define HH    256

// scratch: encoder output z (ln input to slot attention)
__device__ float g_z[BT * DD];

__device__ __forceinline__ float sigmoidf_(float x) { return 1.f / (1.f + __expf(-x)); }

// ---------------------------------------------------------------------------
// Kernel 1: encoder.  z = tanh(gelu(obs@W1+b1)@W2 + obs@skip + b2)
// 8 rows per CTA, 256 threads.
// ---------------------------------------------------------------------------
__global__ __launch_bounds__(256) void enc_kernel(
    const float* __restrict__ obs,
    const float* __restrict__ W1, const float* __restrict__ b1,
    const float* __restrict__ W2, const float* __restrict__ b2,
    const float* __restrict__ skipW)
{
    __shared__ float s_obs[8 * DOBS];   // 16 KB
    __shared__ float s_h[8 * HH];       // 8 KB
    __shared__ float s_p1[8 * DD];      // 4 KB

    const int tid = threadIdx.x;
    const long e0 = (long)blockIdx.x * 8;
    const float* op = obs + e0 * DOBS;

    for (int i = tid; i < 8 * DOBS; i += 256) s_obs[i] = op[i];
    __syncthreads();

    // phase A: h = gelu(obs@W1 + b1), 256 output cols, 8 rows each
    {
        const int j = tid;
        float acc[8];
        const float bj = b1[j];
        #pragma unroll
        for (int r = 0; r < 8; r++) acc[r] = bj;
        for (int k = 0; k < DOBS; k++) {
            const float w = W1[k * HH + j];
            #pragma unroll
            for (int r = 0; r < 8; r++) acc[r] += s_obs[r * DOBS + k] * w;
        }
        #pragma unroll
        for (int r = 0; r < 8; r++) {
            const float a = acc[r];
            s_h[r * HH + j] = 0.5f * a * (1.f + erff(a * 0.70710678118654752f));
        }
    }
    __syncthreads();

    // phase B: z = tanh(h@W2 + obs@skip + b2). split K across two halves.
    const int j = tid & 127;
    const int half = tid >> 7;
    float acc[8];
    #pragma unroll
    for (int r = 0; r < 8; r++) acc[r] = 0.f;

    if (half == 0) {
        for (int k = 0; k < HH; k++) {
            const float w = W2[k * DD + j];
            #pragma unroll
            for (int r = 0; r < 8; r++) acc[r] += s_h[r * HH + k] * w;
        }
        for (int k = 0; k < 128; k++) {
            const float w = skipW[k * DD + j];
            #pragma unroll
            for (int r = 0; r < 8; r++) acc[r] += s_obs[r * DOBS + k] * w;
        }
    } else {
        for (int k = 128; k < DOBS; k++) {
            const float w = skipW[k * DD + j];
            #pragma unroll
            for (int r = 0; r < 8; r++) acc[r] += s_obs[r * DOBS + k] * w;
        }
        #pragma unroll
        for (int r = 0; r < 8; r++) s_p1[r * DD + j] = acc[r];
    }
    __syncthreads();

    if (half == 0) {
        const float bj = b2[j];
        #pragma unroll
        for (int r = 0; r < 8; r++)
            g_z[(e0 + r) * DD + j] = tanhf(acc[r] + s_p1[r * DD + j] + bj);
    }
}

// ---------------------------------------------------------------------------
// helpers for slot kernel
// ---------------------------------------------------------------------------
__device__ __forceinline__ void ln_row128(
    const float* __restrict__ src, float* __restrict__ dst,
    const float* __restrict__ g, const float* __restrict__ bta, int lane)
{
    float x0 = src[lane], x1 = src[lane + 32], x2 = src[lane + 64], x3 = src[lane + 96];
    float s = x0 + x1 + x2 + x3;
    float q = x0 * x0 + x1 * x1 + x2 * x2 + x3 * x3;
    #pragma unroll
    for (int off = 16; off > 0; off >>= 1) {
        s += __shfl_down_sync(0xffffffffu, s, off);
        q += __shfl_down_sync(0xffffffffu, q, off);
    }
    s = __shfl_sync(0xffffffffu, s, 0);
    q = __shfl_sync(0xffffffffu, q, 0);
    const float mu = s * (1.f / 128.f);
    const float var = q * (1.f / 128.f) - mu * mu;
    const float rstd = rsqrtf(var + 1e-5f);
    dst[lane]      = (x0 - mu) * rstd * g[lane]      + bta[lane];
    dst[lane + 32] = (x1 - mu) * rstd * g[lane + 32] + bta[lane + 32];
    dst[lane + 64] = (x2 - mu) * rstd * g[lane + 64] + bta[lane + 64];
    dst[lane + 96] = (x3 - mu) * rstd * g[lane + 96] + bta[lane + 96];
}

__device__ __forceinline__ void norm_store128(
    const float* __restrict__ src, float* __restrict__ dst, int lane)
{
    float x0 = src[lane], x1 = src[lane + 32], x2 = src[lane + 64], x3 = src[lane + 96];
    float q = x0 * x0 + x1 * x1 + x2 * x2 + x3 * x3;
    #pragma unroll
    for (int off = 16; off > 0; off >>= 1) q += __shfl_down_sync(0xffffffffu, q, off);
    q = __shfl_sync(0xffffffffu, q, 0);
    const float inv = 1.f / fmaxf(sqrtf(q), 1e-8f);
    dst[lane]      = x0 * inv;
    dst[lane + 32] = x1 * inv;
    dst[lane + 64] = x2 * inv;
    dst[lane + 96] = x3 * inv;
}

// ---------------------------------------------------------------------------
// Kernel 2: fully fused slot attention, one CTA per (b,t) entry. 384 threads.
// ---------------------------------------------------------------------------
__global__ __launch_bounds__(384) void slot_kernel(
    const float* __restrict__ slot_mu,
    const float* __restrict__ Wk, const float* __restrict__ Wv, const float* __restrict__ Wq,
    const float* __restrict__ Wih, const float* __restrict__ Whh,
    const float* __restrict__ bih, const float* __restrict__ bhh,
    const float* __restrict__ mW1, const float* __restrict__ mb1,
    const float* __restrict__ mW2, const float* __restrict__ mb2,
    const float* __restrict__ lin_g, const float* __restrict__ lin_b,
    const float* __restrict__ lsl_g, const float* __restrict__ lsl_b,
    const float* __restrict__ lml_g, const float* __restrict__ lml_b,
    float* __restrict__ out)
{
    __shared__ float s_inp[DD], s_k[DD], s_v[DD], s_wqk[DD];
    __shared__ float s_vwih[384];
    __shared__ float s_slots[NS * DD];    // 8 KB
    __shared__ float s_u[NS * 384];       // 24 KB union: lns / gh / mlp buffers
    __shared__ float s_partw[4 * DD];
    __shared__ float s_part[4 * NS];
    __shared__ float s_attn[NS];
    __shared__ float s_red[32];

    const int tid = threadIdx.x, lane = tid & 31, warp = tid >> 5;
    const long e = blockIdx.x;
    const float* zrow = g_z + e * DD;

    // ---- LN of z -> s_inp ----
    const float zv = (tid < DD) ? zrow[tid] : 0.f;
    {
        float s1 = zv, s2 = zv * zv;
        #pragma unroll
        for (int off = 16; off > 0; off >>= 1) {
            s1 += __shfl_down_sync(0xffffffffu, s1, off);
            s2 += __shfl_down_sync(0xffffffffu, s2, off);
        }
        if (lane == 0) { s_red[warp] = s1; s_red[12 + warp] = s2; }
    }
    __syncthreads();
    if (tid == 0) {
        float s = s_red[0] + s_red[1] + s_red[2] + s_red[3];
        float q = s_red[12] + s_red[13] + s_red[14] + s_red[15];
        const float mu = s * (1.f / 128.f);
        const float var = q * (1.f / 128.f) - mu * mu;
        s_red[24] = mu;
        s_red[25] = rsqrtf(var + 1e-5f);
    }
    __syncthreads();
    if (tid < DD) s_inp[tid] = (zv - s_red[24]) * s_red[25] * lin_g[tid] + lin_b[tid];
    __syncthreads();

    // ---- k = inp@Wk (threads 0..127), v = inp@Wv (threads 128..255) ----
    if (tid < 256) {
        const int jj = tid & 127;
        const float* W = (tid < 128) ? Wk : Wv;
        float a = 0.f;
        for (int d = 0; d < DD; d++) a += s_inp[d] * W[d * DD + jj];
        if (tid < 128) s_k[jj] = a; else s_v[jj] = a;
    }
    __syncthreads();

    // ---- wqk = Wq @ k (cross-thread reduction, warps 0..3) ----
    if (tid < 128) {
        const float kj = s_k[tid];
        for (int d = 0; d < DD; d++) {
            float v = Wq[d * DD + tid] * kj;
            #pragma unroll
            for (int off = 16; off > 0; off >>= 1) v += __shfl_down_sync(0xffffffffu, v, off);
            if (lane == 0) s_partw[warp * DD + d] = v;
        }
    }
    // ---- vwih = v @ Wih (all 384 threads) ----
    {
        float a = 0.f;
        for (int d = 0; d < DD; d++) a += s_v[d] * Wih[d * 384 + tid];
        s_vwih[tid] = a;
    }
    __syncthreads();
    if (tid < 128)
        s_wqk[tid] = s_partw[tid] + s_partw[DD + tid] + s_partw[2 * DD + tid] + s_partw[3 * DD + tid];
    // ---- init slots ----
    for (int i = tid; i < NS * DD; i += 384) s_slots[i] = slot_mu[i];
    __syncthreads();

    const float invscale = 0.088388347648318447f;  // 1/sqrt(128)
    const int jm = tid & 127;
    const int gidx = tid >> 7;
    const int n0 = (gidx == 0) ? 0 : ((gidx == 1) ? 6 : 11);
    const int nc = (gidx == 0) ? 6 : 5;

    for (int it = 0; it < 3; it++) {
        // (a) lns = ln_sl(slots) -> s_u[0:2048]
        ln_row128(&s_slots[warp * DD], &s_u[warp * DD], lsl_g, lsl_b, lane);
        if (warp < 4)
            ln_row128(&s_slots[(12 + warp) * DD], &s_u[(12 + warp) * DD], lsl_g, lsl_b, lane);
        __syncthreads();

        // (b) logits[n] = lns[n] . wqk  (reduction over 128 threads)
        if (tid < 128) {
            const float wq = s_wqk[tid];
            for (int n = 0; n < NS; n++) {
                float v = s_u[n * DD + tid] * wq;
                #pragma unroll
                for (int off = 16; off > 0; off >>= 1) v += __shfl_down_sync(0xffffffffu, v, off);
                if (lane == 0) s_part[warp * NS + n] = v;
            }
        }
        __syncthreads();
        // (c) softmax over slots
        if (tid == 0) {
            float l[NS]; float mx = -1e30f;
            #pragma unroll
            for (int n = 0; n < NS; n++) {
                const float v = (s_part[n] + s_part[NS + n] + s_part[2 * NS + n] + s_part[3 * NS + n]) * invscale;
                l[n] = v; mx = fmaxf(mx, v);
            }
            float ssum = 0.f;
            #pragma unroll
            for (int n = 0; n < NS; n++) { l[n] = __expf(l[n] - mx); ssum += l[n]; }
            const float inv = 1.f / ssum;
            #pragma unroll
            for (int n = 0; n < NS; n++) s_attn[n] = l[n] * inv;
        }
        __syncthreads();

        // (d) gh = slots @ Whh + bhh  (384 output cols, 16 rows per thread)
        {
            float acc[NS];
            const float bj = bhh[tid];
            #pragma unroll
            for (int n = 0; n < NS; n++) acc[n] = bj;
            for (int d = 0; d < DD; d++) {
                const float w = Whh[d * 384 + tid];
                #pragma unroll
                for (int n = 0; n < NS; n++) acc[n] += s_slots[n * DD + d] * w;
            }
            #pragma unroll
            for (int n = 0; n < NS; n++) s_u[n * 384 + tid] = acc[n];
        }
        __syncthreads();

        // (e) GRU gates; gi[n][d] = attn[n]*vwih[d] + bih[d]
        for (int idx = tid; idx < NS * DD; idx += 384) {
            const int n = idx >> 7, d = idx & 127;
            const float an = s_attn[n];
            const float ir  = an * s_vwih[d]       + bih[d];
            const float iz  = an * s_vwih[d + 128] + bih[d + 128];
            const float inn = an * s_vwih[d + 256] + bih[d + 256];
            const float hr = s_u[n * 384 + d];
            const float hz = s_u[n * 384 + d + 128];
            const float hn = s_u[n * 384 + d + 256];
            const float r  = sigmoidf_(ir + hr);
            const float zg = sigmoidf_(iz + hz);
            const float nn = tanhf(inn + r * hn);
            const float h = s_slots[idx];
            s_slots[idx] = (1.f - zg) * nn + zg * h;
        }
        __syncthreads();

        // (f) mlp-ln -> s_u[0:2048]
        ln_row128(&s_slots[warp * DD], &s_u[warp * DD], lml_g, lml_b, lane);
        if (warp < 4)
            ln_row128(&s_slots[(12 + warp) * DD], &s_u[(12 + warp) * DD], lml_g, lml_b, lane);
        __syncthreads();

        // (g) h1 = relu(sm@W1 + b1) -> s_u[2048:4096]  (disjoint from read region)
        {
            float acc[6];
            #pragma unroll
            for (int r = 0; r < 6; r++) acc[r] = 0.f;
            for (int d = 0; d < DD; d++) {
                const float w = mW1[d * DD + jm];
                #pragma unroll
                for (int r = 0; r < 6; r++)
                    if (r < nc) acc[r] += s_u[(n0 + r) * DD + d] * w;
            }
            const float bj = mb1[jm];
            #pragma unroll
            for (int r = 0; r < 6; r++)
                if (r < nc) s_u[2048 + (n0 + r) * DD + jm] = fmaxf(acc[r] + bj, 0.f);
        }
        __syncthreads();
        // (h) slots += h1@W2 + b2
        {
            float acc[6];
            #pragma unroll
            for (int r = 0; r < 6; r++) acc[r] = 0.f;
            for (int d = 0; d < DD; d++) {
                const float w = mW2[d * DD + jm];
                #pragma unroll
                for (int r = 0; r < 6; r++)
                    if (r < nc) acc[r] += s_u[2048 + (n0 + r) * DD + d] * w;
            }
            const float bj = mb2[jm];
            #pragma unroll
            for (int r = 0; r < 6; r++)
                if (r < nc) s_slots[(n0 + r) * DD + jm] += acc[r] + bj;
        }
        __syncthreads();
    }

    // final F.normalize + write to output
    {
        float* op = out + e * (NS * DD);
        norm_store128(&s_slots[warp * DD], &op[warp * DD], lane);
        if (warp < 4)
            norm_store128(&s_slots[(12 + warp) * DD], &op[(12 + warp) * DD], lane);
    }
}

// ---------------------------------------------------------------------------
// Kernel 3: temporal blend, one step t. out[b,t] = 0.7*out[b,t] + 0.3*tanh(out[b,t-1]@Wt)
// one CTA per batch b (16 slot rows), 128 threads.
// ---------------------------------------------------------------------------
__global__ __launch_bounds__(128) void temporal_kernel(
    float* __restrict__ out, const float* __restrict__ Wt, int t)
{
    __shared__ float s_prev[NS * DD];
    const int j = threadIdx.x;
    const long b = blockIdx.x;
    const float* prev = out + (b * 64 + (t - 1)) * (NS * DD);
    float* cur = out + (b * 64 + t) * (NS * DD);

    for (int i = j; i < NS * DD; i += 128) s_prev[i] = prev[i];
    __syncthreads();

    float acc[NS];
    #pragma unroll
    for (int n = 0; n < NS; n++) acc[n] = 0.f;
    for (int d = 0; d < DD; d++) {
        const float w = Wt[d * DD + j];
        #pragma unroll
        for (int n = 0; n < NS; n++) acc[n] += s_prev[n * DD + d] * w;
    }
    #pragma unroll
    for (int n = 0; n < NS; n++) {
        const float c = cur[n * DD + j];
        cur[n * DD + j] = 0.7f * c + 0.3f * tanhf(acc[n]);
    }
}

// ---------------------------------------------------------------------------
extern "C" void kernel_launch(void* const* d_in, const int* in_sizes, int n_in,
                              void* d_out, int out_size)
{
    const float* obs    = (const float*)d_in[0];
    const float* eW1    = (const float*)d_in[1];
    const float* eb1    = (const float*)d_in[2];
    const float* eW2    = (const float*)d_in[3];
    const float* eb2    = (const float*)d_in[4];
    const float* skipW  = (const float*)d_in[5];
    const float* smu    = (const float*)d_in[6];
    const float* Wk     = (const float*)d_in[7];
    const float* Wv     = (const float*)d_in[8];
    const float* Wq     = (const float*)d_in[9];
    const float* gWih   = (const float*)d_in[10];
    const float* gWhh   = (const float*)d_in[11];
    const float* gbih   = (const float*)d_in[12];
    const float* gbhh   = (const float*)d_in[13];
    const float* mW1    = (const float*)d_in[14];
    const float* mb1    = (const float*)d_in[15];
    const float* mW2    = (const float*)d_in[16];
    const float* mb2    = (const float*)d_in[17];
    const float* lin_g  = (const float*)d_in[18];
    const float* lin_b  = (const float*)d_in[19];
    const float* lsl_g  = (const float*)d_in[20];
    const float* lsl_b  = (const float*)d_in[21];
    const float* lml_g  = (const float*)d_in[22];
    const float* lml_b  = (const float*)d_in[23];
    const float* Wt     = (const float*)d_in[24];
    float* out = (float*)d_out;

    enc_kernel<<<BT / 8, 256>>>(obs, eW1, eb1, eW2, eb2, skipW);

    slot_kernel<<<BT, 384>>>(smu, Wk, Wv, Wq, gWih, gWhh, gbih, gbhh,
                             mW1, mb1, mW2, mb2,
                             lin_g, lin_b, lsl_g, lsl_b, lml_g, lml_b, out);

    for (int t = 1; t < 64; t++)
        temporal_kernel<<<256, 128>>>(out, Wt, t);
}

// round 2
// speedup vs baseline: 1.1095x; 1.1095x over previous
#include <cuda_runtime.h>
#include <math.h>

#define BT    16384
#define DOBS  512
#define DD    128
#define NS    16
#define HH    256

typedef unsigned long long u64;

// packed-f32x2 FMA (FFMA2): d = a*b + c lanewise on (lo,hi) float pairs
__device__ __forceinline__ u64 fma2(u64 a, u64 b, u64 c) {
    u64 d;
    asm("fma.rn.f32x2 %0, %1, %2, %3;" : "=l"(d) : "l"(a), "l"(b), "l"(c));
    return d;
}
__device__ __forceinline__ float sum2(u64 a) {
    float2 f = *(float2*)&a;
    return f.x + f.y;
}
__device__ __forceinline__ u64 pack2(float lo, float hi) {
    u64 r;
    asm("mov.b64 %0, {%1, %2};" : "=l"(r) : "f"(lo), "f"(hi));
    return r;
}
__device__ __forceinline__ float sigmoidf_(float x) { return 1.f / (1.f + __expf(-x)); }

// ---------------- device scratch ----------------
__device__ float g_z[BT * DD];

// pair-interleaved packed weights: p[k4*C + c] = (W[4k4][c],W[4k4+1][c] | W[4k4+2][c],W[4k4+3][c])
__device__ ulonglong2 pW1[128 * 256];   // enc W1  K=512 C=256
__device__ ulonglong2 pW2[64 * 128];    // enc W2  K=256 C=128
__device__ ulonglong2 pSkip[128 * 128]; // skip    K=512 C=128
__device__ ulonglong2 pWk[32 * 128];
__device__ ulonglong2 pWv[32 * 128];
__device__ ulonglong2 pWqT[32 * 128];   // transposed pack of Wq
__device__ ulonglong2 pWih[32 * 384];
__device__ ulonglong2 pWhh[32 * 384];
__device__ ulonglong2 pmW1[32 * 128];
__device__ ulonglong2 pmW2[32 * 128];
__device__ ulonglong2 pWt[32 * 128];

// ---------------- prep: pack weights ----------------
__global__ void pack_kernel(const float* __restrict__ src, ulonglong2* __restrict__ dst,
                            int K4, int C)
{
    int idx = blockIdx.x * blockDim.x + threadIdx.x;
    if (idx >= K4 * C) return;
    int c = idx % C, k4 = idx / C;
    const float* s = src + (4 * k4) * C + c;
    ulonglong2 v;
    v.x = pack2(s[0], s[C]);
    v.y = pack2(s[2 * C], s[3 * C]);
    dst[idx] = v;
}

// transposed pack: dst[j4*K + i] = (W[i][4j4], W[i][4j4+1] | W[i][4j4+2], W[i][4j4+3])
__global__ void packT_kernel(const float* __restrict__ src, ulonglong2* __restrict__ dst,
                             int K, int C4)
{
    int idx = blockIdx.x * blockDim.x + threadIdx.x;
    if (idx >= K * C4) return;
    int i = idx % K, j4 = idx / K;
    const float* s = src + i * (C4 * 4) + 4 * j4;
    ulonglong2 v;
    v.x = pack2(s[0], s[1]);
    v.y = pack2(s[2], s[3]);
    dst[idx] = v;
}

// ---------------------------------------------------------------------------
// Kernel 1: encoder.  z = tanh(gelu(obs@W1+b1)@W2 + obs@skip + b2)
// 8 rows per CTA, 256 threads.
// ---------------------------------------------------------------------------
__global__ __launch_bounds__(256) void enc_kernel(
    const float* __restrict__ obs,
    const float* __restrict__ b1, const float* __restrict__ b2)
{
    __shared__ __align__(16) float s_obs[8 * DOBS];  // 16 KB
    __shared__ __align__(16) float s_h[8 * HH];      // 8 KB
    __shared__ __align__(16) float s_p1[8 * DD];     // 4 KB

    const int tid = threadIdx.x;
    const long e0 = (long)blockIdx.x * 8;
    const float* op = obs + e0 * DOBS;

    for (int i = tid; i < 8 * DOBS / 4; i += 256)
        ((float4*)s_obs)[i] = ((const float4*)op)[i];
    __syncthreads();

    // phase A: h = gelu(obs@W1 + b1)
    {
        const int j = tid;
        u64 acc[8] = {0, 0, 0, 0, 0, 0, 0, 0};
        for (int d4 = 0; d4 < 128; d4++) {
            const ulonglong2 w = pW1[d4 * HH + j];
            #pragma unroll
            for (int r = 0; r < 8; r++) {
                const ulonglong2 s = *(const ulonglong2*)&s_obs[r * DOBS + 4 * d4];
                acc[r] = fma2(s.x, w.x, acc[r]);
                acc[r] = fma2(s.y, w.y, acc[r]);
            }
        }
        const float bj = b1[j];
        #pragma unroll
        for (int r = 0; r < 8; r++) {
            const float a = sum2(acc[r]) + bj;
            s_h[r * HH + j] = 0.5f * a * (1.f + erff(a * 0.70710678118654752f));
        }
    }
    __syncthreads();

    // phase B: z = tanh(h@W2 + obs@skip + b2)
    const int j = tid & 127;
    const int half = tid >> 7;
    u64 acc[8] = {0, 0, 0, 0, 0, 0, 0, 0};

    if (half == 0) {
        for (int d4 = 0; d4 < 64; d4++) {
            const ulonglong2 w = pW2[d4 * DD + j];
            #pragma unroll
            for (int r = 0; r < 8; r++) {
                const ulonglong2 s = *(const ulonglong2*)&s_h[r * HH + 4 * d4];
                acc[r] = fma2(s.x, w.x, acc[r]);
                acc[r] = fma2(s.y, w.y, acc[r]);
            }
        }
        for (int d4 = 0; d4 < 32; d4++) {
            const ulonglong2 w = pSkip[d4 * DD + j];
            #pragma unroll
            for (int r = 0; r < 8; r++) {
                const ulonglong2 s = *(const ulonglong2*)&s_obs[r * DOBS + 4 * d4];
                acc[r] = fma2(s.x, w.x, acc[r]);
                acc[r] = fma2(s.y, w.y, acc[r]);
            }
        }
    } else {
        for (int d4 = 32; d4 < 128; d4++) {
            const ulonglong2 w = pSkip[d4 * DD + j];
            #pragma unroll
            for (int r = 0; r < 8; r++) {
                const ulonglong2 s = *(const ulonglong2*)&s_obs[r * DOBS + 4 * d4];
                acc[r] = fma2(s.x, w.x, acc[r]);
                acc[r] = fma2(s.y, w.y, acc[r]);
            }
        }
        #pragma unroll
        for (int r = 0; r < 8; r++) s_p1[r * DD + j] = sum2(acc[r]);
    }
    __syncthreads();

    if (half == 0) {
        const float bj = b2[j];
        #pragma unroll
        for (int r = 0; r < 8; r++)
            g_z[(e0 + r) * DD + j] = tanhf(sum2(acc[r]) + s_p1[r * DD + j] + bj);
    }
}

// ---------------------------------------------------------------------------
// helpers for slot kernel
// ---------------------------------------------------------------------------
__device__ __forceinline__ void ln_row128(
    const float* __restrict__ src, float* __restrict__ dst,
    const float* __restrict__ g, const float* __restrict__ bta, int lane)
{
    float x0 = src[lane], x1 = src[lane + 32], x2 = src[lane + 64], x3 = src[lane + 96];
    float s = x0 + x1 + x2 + x3;
    float q = x0 * x0 + x1 * x1 + x2 * x2 + x3 * x3;
    #pragma unroll
    for (int off = 16; off > 0; off >>= 1) {
        s += __shfl_down_sync(0xffffffffu, s, off);
        q += __shfl_down_sync(0xffffffffu, q, off);
    }
    s = __shfl_sync(0xffffffffu, s, 0);
    q = __shfl_sync(0xffffffffu, q, 0);
    const float mu = s * (1.f / 128.f);
    const float var = q * (1.f / 128.f) - mu * mu;
    const float rstd = rsqrtf(var + 1e-5f);
    dst[lane]      = (x0 - mu) * rstd * g[lane]      + bta[lane];
    dst[lane + 32] = (x1 - mu) * rstd * g[lane + 32] + bta[lane + 32];
    dst[lane + 64] = (x2 - mu) * rstd * g[lane + 64] + bta[lane + 64];
    dst[lane + 96] = (x3 - mu) * rstd * g[lane + 96] + bta[lane + 96];
}

__device__ __forceinline__ void norm_store128(
    const float* __restrict__ src, float* __restrict__ dst, int lane)
{
    float x0 = src[lane], x1 = src[lane + 32], x2 = src[lane + 64], x3 = src[lane + 96];
    float q = x0 * x0 + x1 * x1 + x2 * x2 + x3 * x3;
    #pragma unroll
    for (int off = 16; off > 0; off >>= 1) q += __shfl_down_sync(0xffffffffu, q, off);
    q = __shfl_sync(0xffffffffu, q, 0);
    const float inv = 1.f / fmaxf(sqrtf(q), 1e-8f);
    dst[lane]      = x0 * inv;
    dst[lane + 32] = x1 * inv;
    dst[lane + 64] = x2 * inv;
    dst[lane + 96] = x3 * inv;
}

// ---------------------------------------------------------------------------
// Kernel 2: fully fused slot attention, one CTA per (b,t) entry. 384 threads.
// ---------------------------------------------------------------------------
__global__ __launch_bounds__(384) void slot_kernel(
    const float* __restrict__ slot_mu,
    const float* __restrict__ bih, const float* __restrict__ bhh,
    const float* __restrict__ mb1, const float* __restrict__ mb2,
    const float* __restrict__ lin_g, const float* __restrict__ lin_b,
    const float* __restrict__ lsl_g, const float* __restrict__ lsl_b,
    const float* __restrict__ lml_g, const float* __restrict__ lml_b,
    float* __restrict__ out)
{
    __shared__ __align__(16) float s_inp[DD], s_k[DD], s_v[DD], s_wqk[DD];
    __shared__ __align__(16) float s_vwih[384];
    __shared__ __align__(16) float s_slots[NS * DD];  // 8 KB
    __shared__ __align__(16) float s_u[NS * 384];     // 24 KB (lns / gh / mlp buffers)
    __shared__ float s_part[4 * NS];
    __shared__ float s_attn[NS];
    __shared__ float s_red[32];

    const int tid = threadIdx.x, lane = tid & 31, warp = tid >> 5;
    const long e = blockIdx.x;
    const float* zrow = g_z + e * DD;

    // ---- LN of z -> s_inp ----
    const float zv = (tid < DD) ? zrow[tid] : 0.f;
    {
        float s1 = zv, s2 = zv * zv;
        #pragma unroll
        for (int off = 16; off > 0; off >>= 1) {
            s1 += __shfl_down_sync(0xffffffffu, s1, off);
            s2 += __shfl_down_sync(0xffffffffu, s2, off);
        }
        if (lane == 0) { s_red[warp] = s1; s_red[12 + warp] = s2; }
    }
    __syncthreads();
    if (tid == 0) {
        float s = s_red[0] + s_red[1] + s_red[2] + s_red[3];
        float q = s_red[12] + s_red[13] + s_red[14] + s_red[15];
        const float mu = s * (1.f / 128.f);
        const float var = q * (1.f / 128.f) - mu * mu;
        s_red[24] = mu;
        s_red[25] = rsqrtf(var + 1e-5f);
    }
    __syncthreads();
    if (tid < DD) s_inp[tid] = (zv - s_red[24]) * s_red[25] * lin_g[tid] + lin_b[tid];
    __syncthreads();

    // ---- k = inp@Wk (threads 0..127), v = inp@Wv (threads 128..255) ----
    if (tid < 256) {
        const int jj = tid & 127;
        const ulonglong2* W = (tid < 128) ? pWk : pWv;
        u64 acc = 0;
        for (int d4 = 0; d4 < 32; d4++) {
            const ulonglong2 s = *(const ulonglong2*)&s_inp[4 * d4];
            const ulonglong2 w = W[d4 * DD + jj];
            acc = fma2(s.x, w.x, acc);
            acc = fma2(s.y, w.y, acc);
        }
        if (tid < 128) s_k[jj] = sum2(acc); else s_v[jj] = sum2(acc);
    }
    __syncthreads();

    // ---- wqk[i] = sum_j Wq[i][j] * k[j]  (thread i, coalesced packed loads) ----
    if (tid < 128) {
        u64 acc = 0;
        for (int j4 = 0; j4 < 32; j4++) {
            const ulonglong2 s = *(const ulonglong2*)&s_k[4 * j4];
            const ulonglong2 w = pWqT[j4 * DD + tid];
            acc = fma2(s.x, w.x, acc);
            acc = fma2(s.y, w.y, acc);
        }
        s_wqk[tid] = sum2(acc);
    }
    // ---- vwih = v @ Wih (all 384 threads) ----
    {
        u64 acc = 0;
        for (int d4 = 0; d4 < 32; d4++) {
            const ulonglong2 s = *(const ulonglong2*)&s_v[4 * d4];
            const ulonglong2 w = pWih[d4 * 384 + tid];
            acc = fma2(s.x, w.x, acc);
            acc = fma2(s.y, w.y, acc);
        }
        s_vwih[tid] = sum2(acc);
    }
    // ---- init slots ----
    for (int i = tid; i < NS * DD; i += 384) s_slots[i] = slot_mu[i];
    __syncthreads();

    const float invscale = 0.088388347648318447f;  // 1/sqrt(128)
    const int jm = tid & 127;
    const int gidx = tid >> 7;
    const int n0 = (gidx == 0) ? 0 : ((gidx == 1) ? 6 : 11);
    const int nc = (gidx == 0) ? 6 : 5;
    const float bhh_j = bhh[tid];
    const float mb1_j = mb1[jm];
    const float mb2_j = mb2[jm];

    for (int it = 0; it < 3; it++) {
        // (a) lns = ln_sl(slots) -> s_u[0:2048]
        ln_row128(&s_slots[warp * DD], &s_u[warp * DD], lsl_g, lsl_b, lane);
        if (warp < 4)
            ln_row128(&s_slots[(12 + warp) * DD], &s_u[(12 + warp) * DD], lsl_g, lsl_b, lane);
        __syncthreads();

        // (b) logits[n] = lns[n] . wqk
        if (tid < 128) {
            const float wq = s_wqk[tid];
            for (int n = 0; n < NS; n++) {
                float v = s_u[n * DD + tid] * wq;
                #pragma unroll
                for (int off = 16; off > 0; off >>= 1) v += __shfl_down_sync(0xffffffffu, v, off);
                if (lane == 0) s_part[warp * NS + n] = v;
            }
        }
        __syncthreads();
        // (c) softmax over slots
        if (tid == 0) {
            float l[NS]; float mx = -1e30f;
            #pragma unroll
            for (int n = 0; n < NS; n++) {
                const float v = (s_part[n] + s_part[NS + n] + s_part[2 * NS + n] + s_part[3 * NS + n]) * invscale;
                l[n] = v; mx = fmaxf(mx, v);
            }
            float ssum = 0.f;
            #pragma unroll
            for (int n = 0; n < NS; n++) { l[n] = __expf(l[n] - mx); ssum += l[n]; }
            const float inv = 1.f / ssum;
            #pragma unroll
            for (int n = 0; n < NS; n++) s_attn[n] = l[n] * inv;
        }
        __syncthreads();

        // (d) gh = slots @ Whh + bhh
        {
            u64 acc[NS];
            #pragma unroll
            for (int n = 0; n < NS; n++) acc[n] = 0;
            for (int d4 = 0; d4 < 32; d4++) {
                const ulonglong2 w = pWhh[d4 * 384 + tid];
                #pragma unroll
                for (int n = 0; n < NS; n++) {
                    const ulonglong2 s = *(const ulonglong2*)&s_slots[n * DD + 4 * d4];
                    acc[n] = fma2(s.x, w.x, acc[n]);
                    acc[n] = fma2(s.y, w.y, acc[n]);
                }
            }
            #pragma unroll
            for (int n = 0; n < NS; n++) s_u[n * 384 + tid] = sum2(acc[n]) + bhh_j;
        }
        __syncthreads();

        // (e) GRU gates
        for (int idx = tid; idx < NS * DD; idx += 384) {
            const int n = idx >> 7, d = idx & 127;
            const float an = s_attn[n];
            const float ir  = an * s_vwih[d]       + bih[d];
            const float iz  = an * s_vwih[d + 128] + bih[d + 128];
            const float inn = an * s_vwih[d + 256] + bih[d + 256];
            const float hr = s_u[n * 384 + d];
            const float hz = s_u[n * 384 + d + 128];
            const float hn = s_u[n * 384 + d + 256];
            const float r  = sigmoidf_(ir + hr);
            const float zg = sigmoidf_(iz + hz);
            const float nn = tanhf(inn + r * hn);
            const float h = s_slots[idx];
            s_slots[idx] = (1.f - zg) * nn + zg * h;
        }
        __syncthreads();

        // (f) mlp-ln -> s_u[0:2048]
        ln_row128(&s_slots[warp * DD], &s_u[warp * DD], lml_g, lml_b, lane);
        if (warp < 4)
            ln_row128(&s_slots[(12 + warp) * DD], &s_u[(12 + warp) * DD], lml_g, lml_b, lane);
        __syncthreads();

        // (g) h1 = relu(sm@W1 + b1) -> s_u[2048:4096]
        {
            u64 acc[6] = {0, 0, 0, 0, 0, 0};
            for (int d4 = 0; d4 < 32; d4++) {
                const ulonglong2 w = pmW1[d4 * DD + jm];
                #pragma unroll
                for (int r = 0; r < 6; r++)
                    if (r < nc) {
                        const ulonglong2 s = *(const ulonglong2*)&s_u[(n0 + r) * DD + 4 * d4];
                        acc[r] = fma2(s.x, w.x, acc[r]);
                        acc[r] = fma2(s.y, w.y, acc[r]);
                    }
            }
            #pragma unroll
            for (int r = 0; r < 6; r++)
                if (r < nc) s_u[2048 + (n0 + r) * DD + jm] = fmaxf(sum2(acc[r]) + mb1_j, 0.f);
        }
        __syncthreads();
        // (h) slots += h1@W2 + b2
        {
            u64 acc[6] = {0, 0, 0, 0, 0, 0};
            for (int d4 = 0; d4 < 32; d4++) {
                const ulonglong2 w = pmW2[d4 * DD + jm];
                #pragma unroll
                for (int r = 0; r < 6; r++)
                    if (r < nc) {
                        const ulonglong2 s = *(const ulonglong2*)&s_u[2048 + (n0 + r) * DD + 4 * d4];
                        acc[r] = fma2(s.x, w.x, acc[r]);
                        acc[r] = fma2(s.y, w.y, acc[r]);
                    }
            }
            #pragma unroll
            for (int r = 0; r < 6; r++)
                if (r < nc) s_slots[(n0 + r) * DD + jm] += sum2(acc[r]) + mb2_j;
        }
        __syncthreads();
    }

    // final F.normalize + write to output
    {
        float* op = out + e * (NS * DD);
        norm_store128(&s_slots[warp * DD], &op[warp * DD], lane);
        if (warp < 4)
            norm_store128(&s_slots[(12 + warp) * DD], &op[(12 + warp) * DD], lane);
    }
}

// ---------------------------------------------------------------------------
// Kernel 3: persistent temporal blend. One CTA per batch b, loops t=1..63.
// out[b,t] = 0.7*out[b,t] + 0.3*tanh(prev @ Wt); prev kept in smem.
// 512 threads = 128 cols x 4 slot-groups of 4.
// ---------------------------------------------------------------------------
__global__ __launch_bounds__(512) void temporal_kernel(
    float* __restrict__ out)
{
    __shared__ __align__(16) float s_prev[NS * DD];
    const int tid = threadIdx.x;
    const int j = tid & 127;
    const int g = tid >> 7;  // 0..3, rows g*4 .. g*4+3
    const long b = blockIdx.x;
    float* base = out + b * 64 * (NS * DD);

    for (int i = tid; i < NS * DD; i += 512) s_prev[i] = base[i];
    __syncthreads();

    for (int t = 1; t < 64; t++) {
        float* cur = base + t * (NS * DD);
        float c[4];
        #pragma unroll
        for (int r = 0; r < 4; r++) c[r] = cur[(g * 4 + r) * DD + j];

        u64 acc[4] = {0, 0, 0, 0};
        for (int d4 = 0; d4 < 32; d4++) {
            const ulonglong2 w = pWt[d4 * DD + j];
            #pragma unroll
            for (int r = 0; r < 4; r++) {
                const ulonglong2 s = *(const ulonglong2*)&s_prev[(g * 4 + r) * DD + 4 * d4];
                acc[r] = fma2(s.x, w.x, acc[r]);
                acc[r] = fma2(s.y, w.y, acc[r]);
            }
        }
        __syncthreads();  // all reads of s_prev complete before overwrite
        #pragma unroll
        for (int r = 0; r < 4; r++) {
            const float v = 0.7f * c[r] + 0.3f * tanhf(sum2(acc[r]));
            cur[(g * 4 + r) * DD + j] = v;
            s_prev[(g * 4 + r) * DD + j] = v;
        }
        __syncthreads();
    }
}

// ---------------------------------------------------------------------------
extern "C" void kernel_launch(void* const* d_in, const int* in_sizes, int n_in,
                              void* d_out, int out_size)
{
    const float* obs    = (const float*)d_in[0];
    const float* eW1    = (const float*)d_in[1];
    const float* eb1    = (const float*)d_in[2];
    const float* eW2    = (const float*)d_in[3];
    const float* eb2    = (const float*)d_in[4];
    const float* skipW  = (const float*)d_in[5];
    const float* smu    = (const float*)d_in[6];
    const float* Wk     = (const float*)d_in[7];
    const float* Wv     = (const float*)d_in[8];
    const float* Wq     = (const float*)d_in[9];
    const float* gWih   = (const float*)d_in[10];
    const float* gWhh   = (const float*)d_in[11];
    const float* gbih   = (const float*)d_in[12];
    const float* gbhh   = (const float*)d_in[13];
    const float* mW1    = (const float*)d_in[14];
    const float* mb1    = (const float*)d_in[15];
    const float* mW2    = (const float*)d_in[16];
    const float* mb2    = (const float*)d_in[17];
    const float* lin_g  = (const float*)d_in[18];
    const float* lin_b  = (const float*)d_in[19];
    const float* lsl_g  = (const float*)d_in[20];
    const float* lsl_b  = (const float*)d_in[21];
    const float* lml_g  = (const float*)d_in[22];
    const float* lml_b  = (const float*)d_in[23];
    const float* Wt     = (const float*)d_in[24];
    float* out = (float*)d_out;

    ulonglong2 *dW1, *dW2, *dSkip, *dWk, *dWv, *dWqT, *dWih, *dWhh, *dmW1, *dmW2, *dWt;
    cudaGetSymbolAddress((void**)&dW1,   pW1);
    cudaGetSymbolAddress((void**)&dW2,   pW2);
    cudaGetSymbolAddress((void**)&dSkip, pSkip);
    cudaGetSymbolAddress((void**)&dWk,   pWk);
    cudaGetSymbolAddress((void**)&dWv,   pWv);
    cudaGetSymbolAddress((void**)&dWqT,  pWqT);
    cudaGetSymbolAddress((void**)&dWih,  pWih);
    cudaGetSymbolAddress((void**)&dWhh,  pWhh);
    cudaGetSymbolAddress((void**)&dmW1,  pmW1);
    cudaGetSymbolAddress((void**)&dmW2,  pmW2);
    cudaGetSymbolAddress((void**)&dWt,   pWt);

    // pack weights (pair-interleaved for FFMA2)
    pack_kernel<<<(128 * 256 + 255) / 256, 256>>>(eW1,   dW1,   128, 256);
    pack_kernel<<<(64 * 128 + 255) / 256, 256>>>(eW2,    dW2,   64, 128);
    pack_kernel<<<(128 * 128 + 255) / 256, 256>>>(skipW, dSkip, 128, 128);
    pack_kernel<<<(32 * 128 + 255) / 256, 256>>>(Wk,     dWk,   32, 128);
    pack_kernel<<<(32 * 128 + 255) / 256, 256>>>(Wv,     dWv,   32, 128);
    packT_kernel<<<(128 * 32 + 255) / 256, 256>>>(Wq,    dWqT,  128, 32);
    pack_kernel<<<(32 * 384 + 255) / 256, 256>>>(gWih,   dWih,  32, 384);
    pack_kernel<<<(32 * 384 + 255) / 256, 256>>>(gWhh,   dWhh,  32, 384);
    pack_kernel<<<(32 * 128 + 255) / 256, 256>>>(mW1,    dmW1,  32, 128);
    pack_kernel<<<(32 * 128 + 255) / 256, 256>>>(mW2,    dmW2,  32, 128);
    pack_kernel<<<(32 * 128 + 255) / 256, 256>>>(Wt,     dWt,   32, 128);

    enc_kernel<<<BT / 8, 256>>>(obs, eb1, eb2);

    slot_kernel<<<BT, 384>>>(smu, gbih, gbhh, mb1, mb2,
                             lin_g, lin_b, lsl_g, lsl_b, lml_g, lml_b, out);

    temporal_kernel<<<256, 512>>>(out);
}

// round 3
// speedup vs baseline: 1.6001x; 1.4422x over previous
#include <cuda_runtime.h>
#include <math.h>

#define BT    16384
#define DOBS  512
#define DD    128
#define NS    16
#define HH    256

typedef unsigned long long u64;

// packed-f32x2 FMA (FFMA2): d = a*b + c lanewise on (lo,hi) float pairs
__device__ __forceinline__ u64 fma2(u64 a, u64 b, u64 c) {
    u64 d;
    asm("fma.rn.f32x2 %0, %1, %2, %3;" : "=l"(d) : "l"(a), "l"(b), "l"(c));
    return d;
}
__device__ __forceinline__ float sum2(u64 a) {
    float2 f = *(float2*)&a;
    return f.x + f.y;
}
__device__ __forceinline__ u64 pack2(float lo, float hi) {
    u64 r;
    asm("mov.b64 %0, {%1, %2};" : "=l"(r) : "f"(lo), "f"(hi));
    return r;
}
__device__ __forceinline__ float tanha(float x) {
    float y;
    asm("tanh.approx.f32 %0, %1;" : "=f"(y) : "f"(x));
    return y;
}
__device__ __forceinline__ float sigm(float x) { return 0.5f * tanha(0.5f * x) + 0.5f; }

// ---------------- device scratch ----------------
__device__ float g_z[BT * DD];

// pair-interleaved packed weights: p[k4*C + c] = (W[4k4][c],W[4k4+1][c] | W[4k4+2][c],W[4k4+3][c])
__device__ ulonglong2 pW1[128 * 256];
__device__ ulonglong2 pW2[64 * 128];
__device__ ulonglong2 pSkip[128 * 128];
__device__ ulonglong2 pWk[32 * 128];
__device__ ulonglong2 pWv[32 * 128];
__device__ ulonglong2 pWqT[32 * 128];   // transposed pack of Wq
__device__ ulonglong2 pWih[32 * 384];
__device__ ulonglong2 pWhh[32 * 384];
__device__ ulonglong2 pmW1[32 * 128];
__device__ ulonglong2 pmW2[32 * 128];
__device__ ulonglong2 pWt[32 * 128];

// ---------------- fused pack kernel ----------------
__device__ __forceinline__ void pack_elem(const float* __restrict__ src,
                                          ulonglong2* __restrict__ dst,
                                          int C, int idx)
{
    int c = idx % C, k4 = idx / C;
    const float* s = src + (4 * k4) * C + c;
    ulonglong2 v;
    v.x = pack2(s[0], s[C]);
    v.y = pack2(s[2 * C], s[3 * C]);
    dst[idx] = v;
}
__device__ __forceinline__ void packT_elem(const float* __restrict__ src,
                                           ulonglong2* __restrict__ dst,
                                           int K, int C4, int idx)
{
    int i = idx % K, j4 = idx / K;
    const float* s = src + i * (C4 * 4) + 4 * j4;
    ulonglong2 v;
    v.x = pack2(s[0], s[1]);
    v.y = pack2(s[2], s[3]);
    dst[idx] = v;
}

__global__ __launch_bounds__(256) void pack_all(
    const float* __restrict__ eW1, const float* __restrict__ eW2,
    const float* __restrict__ skipW,
    const float* __restrict__ Wk, const float* __restrict__ Wv,
    const float* __restrict__ Wq,
    const float* __restrict__ gWih, const float* __restrict__ gWhh,
    const float* __restrict__ mW1, const float* __restrict__ mW2,
    const float* __restrict__ Wt)
{
    int idx = blockIdx.x * 256 + threadIdx.x;
    if (idx < 32768) { pack_elem(eW1,  pW1,  256, idx); return; }  idx -= 32768;
    if (idx < 8192)  { pack_elem(eW2,  pW2,  128, idx); return; }  idx -= 8192;
    if (idx < 16384) { pack_elem(skipW,pSkip,128, idx); return; }  idx -= 16384;
    if (idx < 4096)  { pack_elem(Wk,   pWk,  128, idx); return; }  idx -= 4096;
    if (idx < 4096)  { pack_elem(Wv,   pWv,  128, idx); return; }  idx -= 4096;
    if (idx < 4096)  { packT_elem(Wq,  pWqT, 128, 32, idx); return; } idx -= 4096;
    if (idx < 12288) { pack_elem(gWih, pWih, 384, idx); return; }  idx -= 12288;
    if (idx < 12288) { pack_elem(gWhh, pWhh, 384, idx); return; }  idx -= 12288;
    if (idx < 4096)  { pack_elem(mW1,  pmW1, 128, idx); return; }  idx -= 4096;
    if (idx < 4096)  { pack_elem(mW2,  pmW2, 128, idx); return; }  idx -= 4096;
    if (idx < 4096)  { pack_elem(Wt,   pWt,  128, idx); return; }
}

// ---------------------------------------------------------------------------
// Kernel 1: encoder.  z = tanh(gelu(obs@W1+b1)@W2 + obs@skip + b2)
// 8 rows per CTA, 256 threads.
// ---------------------------------------------------------------------------
__global__ __launch_bounds__(256) void enc_kernel(
    const float* __restrict__ obs,
    const float* __restrict__ b1, const float* __restrict__ b2)
{
    __shared__ __align__(16) float s_obs[8 * DOBS];
    __shared__ __align__(16) float s_h[8 * HH];
    __shared__ __align__(16) float s_p1[8 * DD];

    const int tid = threadIdx.x;
    const long e0 = (long)blockIdx.x * 8;
    const float* op = obs + e0 * DOBS;

    for (int i = tid; i < 8 * DOBS / 4; i += 256)
        ((float4*)s_obs)[i] = ((const float4*)op)[i];
    __syncthreads();

    // phase A: h = gelu(obs@W1 + b1)
    {
        const int j = tid;
        u64 acc[8] = {0, 0, 0, 0, 0, 0, 0, 0};
        for (int d4 = 0; d4 < 128; d4++) {
            const ulonglong2 w = pW1[d4 * HH + j];
            #pragma unroll
            for (int r = 0; r < 8; r++) {
                const ulonglong2 s = *(const ulonglong2*)&s_obs[r * DOBS + 4 * d4];
                acc[r] = fma2(s.x, w.x, acc[r]);
                acc[r] = fma2(s.y, w.y, acc[r]);
            }
        }
        const float bj = b1[j];
        #pragma unroll
        for (int r = 0; r < 8; r++) {
            const float a = sum2(acc[r]) + bj;
            s_h[r * HH + j] = 0.5f * a * (1.f + erff(a * 0.70710678118654752f));
        }
    }
    __syncthreads();

    // phase B: z = tanh(h@W2 + obs@skip + b2)
    const int j = tid & 127;
    const int half = tid >> 7;
    u64 acc[8] = {0, 0, 0, 0, 0, 0, 0, 0};

    if (half == 0) {
        for (int d4 = 0; d4 < 64; d4++) {
            const ulonglong2 w = pW2[d4 * DD + j];
            #pragma unroll
            for (int r = 0; r < 8; r++) {
                const ulonglong2 s = *(const ulonglong2*)&s_h[r * HH + 4 * d4];
                acc[r] = fma2(s.x, w.x, acc[r]);
                acc[r] = fma2(s.y, w.y, acc[r]);
            }
        }
        for (int d4 = 0; d4 < 32; d4++) {
            const ulonglong2 w = pSkip[d4 * DD + j];
            #pragma unroll
            for (int r = 0; r < 8; r++) {
                const ulonglong2 s = *(const ulonglong2*)&s_obs[r * DOBS + 4 * d4];
                acc[r] = fma2(s.x, w.x, acc[r]);
                acc[r] = fma2(s.y, w.y, acc[r]);
            }
        }
    } else {
        for (int d4 = 32; d4 < 128; d4++) {
            const ulonglong2 w = pSkip[d4 * DD + j];
            #pragma unroll
            for (int r = 0; r < 8; r++) {
                const ulonglong2 s = *(const ulonglong2*)&s_obs[r * DOBS + 4 * d4];
                acc[r] = fma2(s.x, w.x, acc[r]);
                acc[r] = fma2(s.y, w.y, acc[r]);
            }
        }
        #pragma unroll
        for (int r = 0; r < 8; r++) s_p1[r * DD + j] = sum2(acc[r]);
    }
    __syncthreads();

    if (half == 0) {
        const float bj = b2[j];
        #pragma unroll
        for (int r = 0; r < 8; r++)
            g_z[(e0 + r) * DD + j] = tanha(sum2(acc[r]) + s_p1[r * DD + j] + bj);
    }
}

// ---------------------------------------------------------------------------
__device__ __forceinline__ void norm_store128(
    const float* __restrict__ src, float* __restrict__ dst, int lane)
{
    float x0 = src[lane], x1 = src[lane + 32], x2 = src[lane + 64], x3 = src[lane + 96];
    float q = x0 * x0 + x1 * x1 + x2 * x2 + x3 * x3;
    #pragma unroll
    for (int off = 16; off > 0; off >>= 1) q += __shfl_down_sync(0xffffffffu, q, off);
    q = __shfl_sync(0xffffffffu, q, 0);
    const float inv = 1.f / fmaxf(sqrtf(q), 1e-8f);
    dst[lane]      = x0 * inv;
    dst[lane + 32] = x1 * inv;
    dst[lane + 64] = x2 * inv;
    dst[lane + 96] = x3 * inv;
}

// ---------------------------------------------------------------------------
// Kernel 2: fused slot attention, one CTA per (b,t). 512 threads = 16 warps.
// thread (j = tid&127, g = tid>>7) owns column j of slot rows 4g..4g+3.
// warp w owns slot row w for LN / logits / final normalize.
// ---------------------------------------------------------------------------
__global__ __launch_bounds__(512, 2) void slot_kernel(
    const float* __restrict__ slot_mu,
    const float* __restrict__ bih, const float* __restrict__ bhh,
    const float* __restrict__ mb1, const float* __restrict__ mb2,
    const float* __restrict__ lin_g, const float* __restrict__ lin_b,
    const float* __restrict__ lsl_g, const float* __restrict__ lsl_b,
    const float* __restrict__ lml_g, const float* __restrict__ lml_b,
    float* __restrict__ out)
{
    __shared__ __align__(16) float s_inp[DD], s_k[DD], s_v[DD], s_wqk[DD];
    __shared__ __align__(16) float s_vwih[384];
    __shared__ __align__(16) float s_slots[NS * DD];   // 8 KB
    __shared__ __align__(16) float s_ln[NS * DD];      // 8 KB
    __shared__ __align__(16) float s_h1[NS * DD];      // 8 KB
    __shared__ __align__(16) float s_lnp[512];         // [lsl_g|lsl_b|lml_g|lml_b]
    __shared__ float s_attn[NS], s_logits[NS];
    __shared__ float s_red[20];

    const int tid = threadIdx.x, lane = tid & 31, warp = tid >> 5;
    const int j = tid & 127, g = tid >> 7;
    const long e = blockIdx.x;

    // ---- LN of z -> s_inp (warps 0..3) ----
    const float zv = (tid < DD) ? g_z[e * DD + tid] : 0.f;
    if (tid < DD) {
        float s1 = zv, s2 = zv * zv;
        #pragma unroll
        for (int off = 16; off > 0; off >>= 1) {
            s1 += __shfl_down_sync(0xffffffffu, s1, off);
            s2 += __shfl_down_sync(0xffffffffu, s2, off);
        }
        if (lane == 0) { s_red[warp] = s1; s_red[8 + warp] = s2; }
    }
    __syncthreads();
    if (tid == 0) {
        float s = s_red[0] + s_red[1] + s_red[2] + s_red[3];
        float q = s_red[8] + s_red[9] + s_red[10] + s_red[11];
        const float mu = s * (1.f / 128.f);
        const float var = q * (1.f / 128.f) - mu * mu;
        s_red[16] = mu;
        s_red[17] = rsqrtf(var + 1e-5f);
    }
    __syncthreads();
    if (tid < DD) s_inp[tid] = (zv - s_red[16]) * s_red[17] * lin_g[tid] + lin_b[tid];
    __syncthreads();

    // ---- k (g==0), v (g==1); slots init + ln params copy (g>=2) ----
    if (g == 0 || g == 1) {
        const ulonglong2* W = (g == 0) ? pWk : pWv;
        u64 acc = 0;
        for (int d4 = 0; d4 < 32; d4++) {
            const ulonglong2 s = *(const ulonglong2*)&s_inp[4 * d4];
            const ulonglong2 w = W[d4 * DD + j];
            acc = fma2(s.x, w.x, acc);
            acc = fma2(s.y, w.y, acc);
        }
        if (g == 0) s_k[j] = sum2(acc); else s_v[j] = sum2(acc);
    } else if (g == 2) {
        const int t2 = tid - 256;  // 0..127
        ((float4*)s_slots)[t2]       = ((const float4*)slot_mu)[t2];
        ((float4*)s_slots)[t2 + 128] = ((const float4*)slot_mu)[t2 + 128];
        ((float4*)s_slots)[t2 + 256] = ((const float4*)slot_mu)[t2 + 256];
        ((float4*)s_slots)[t2 + 384] = ((const float4*)slot_mu)[t2 + 384];
    } else {
        const int t3 = tid - 384;  // 0..127
        if (t3 < 32)       ((float4*)s_lnp)[t3]      = ((const float4*)lsl_g)[t3];
        else if (t3 < 64)  ((float4*)s_lnp)[t3]      = ((const float4*)lsl_b)[t3 - 32];
        else if (t3 < 96)  ((float4*)s_lnp)[t3]      = ((const float4*)lml_g)[t3 - 64];
        else               ((float4*)s_lnp)[t3]      = ((const float4*)lml_b)[t3 - 96];
    }
    __syncthreads();

    // ---- wqk (tid<128), vwih (tid>=128) ----
    if (tid < DD) {
        u64 acc = 0;
        for (int j4 = 0; j4 < 32; j4++) {
            const ulonglong2 s = *(const ulonglong2*)&s_k[4 * j4];
            const ulonglong2 w = pWqT[j4 * DD + tid];
            acc = fma2(s.x, w.x, acc);
            acc = fma2(s.y, w.y, acc);
        }
        s_wqk[tid] = sum2(acc);
    } else {
        const int c = tid - DD;  // 0..383
        u64 acc = 0;
        for (int d4 = 0; d4 < 32; d4++) {
            const ulonglong2 s = *(const ulonglong2*)&s_v[4 * d4];
            const ulonglong2 w = pWih[d4 * 384 + c];
            acc = fma2(s.x, w.x, acc);
            acc = fma2(s.y, w.y, acc);
        }
        s_vwih[c] = sum2(acc);
    }
    __syncthreads();

    const float invscale = 0.088388347648318447f;  // 1/sqrt(128)

    for (int it = 0; it < 3; it++) {
        // (a+b) LN(slots) fused with logit dot — warp w owns row w
        {
            const float* src = &s_slots[warp * DD];
            float x0 = src[lane], x1 = src[lane + 32], x2 = src[lane + 64], x3 = src[lane + 96];
            float s = x0 + x1 + x2 + x3;
            float q = x0 * x0 + x1 * x1 + x2 * x2 + x3 * x3;
            #pragma unroll
            for (int off = 16; off > 0; off >>= 1) {
                s += __shfl_down_sync(0xffffffffu, s, off);
                q += __shfl_down_sync(0xffffffffu, q, off);
            }
            s = __shfl_sync(0xffffffffu, s, 0);
            q = __shfl_sync(0xffffffffu, q, 0);
            const float mu = s * (1.f / 128.f);
            const float rstd = rsqrtf(q * (1.f / 128.f) - mu * mu + 1e-5f);
            const float n0 = (x0 - mu) * rstd * s_lnp[lane]      + s_lnp[128 + lane];
            const float n1 = (x1 - mu) * rstd * s_lnp[lane + 32] + s_lnp[160 + lane];
            const float n2 = (x2 - mu) * rstd * s_lnp[lane + 64] + s_lnp[192 + lane];
            const float n3 = (x3 - mu) * rstd * s_lnp[lane + 96] + s_lnp[224 + lane];
            float p = n0 * s_wqk[lane] + n1 * s_wqk[lane + 32]
                    + n2 * s_wqk[lane + 64] + n3 * s_wqk[lane + 96];
            #pragma unroll
            for (int off = 16; off > 0; off >>= 1) p += __shfl_down_sync(0xffffffffu, p, off);
            if (lane == 0) s_logits[warp] = p * invscale;
        }
        __syncthreads();
        // (c) softmax over 16 slots — warp 0, lanes 0..15
        if (warp == 0 && lane < 16) {
            const float l = s_logits[lane];
            float m = l;
            #pragma unroll
            for (int off = 8; off > 0; off >>= 1)
                m = fmaxf(m, __shfl_xor_sync(0xffffu, m, off));
            const float ex = __expf(l - m);
            float ssum = ex;
            #pragma unroll
            for (int off = 8; off > 0; off >>= 1)
                ssum += __shfl_xor_sync(0xffffu, ssum, off);
            s_attn[lane] = ex / ssum;
        }
        __syncthreads();

        // (d) GRU: gh = slots@Whh (+bhh) fully in registers, then gate math
        {
            u64 ar[4] = {0, 0, 0, 0}, az[4] = {0, 0, 0, 0}, an[4] = {0, 0, 0, 0};
            for (int d4 = 0; d4 < 32; d4++) {
                const ulonglong2 wr = pWhh[d4 * 384 + j];
                const ulonglong2 wz = pWhh[d4 * 384 + j + 128];
                const ulonglong2 wn = pWhh[d4 * 384 + j + 256];
                #pragma unroll
                for (int r = 0; r < 4; r++) {
                    const ulonglong2 sv = *(const ulonglong2*)&s_slots[(4 * g + r) * DD + 4 * d4];
                    ar[r] = fma2(sv.x, wr.x, ar[r]);
                    ar[r] = fma2(sv.y, wr.y, ar[r]);
                    az[r] = fma2(sv.x, wz.x, az[r]);
                    az[r] = fma2(sv.y, wz.y, az[r]);
                    an[r] = fma2(sv.x, wn.x, an[r]);
                    an[r] = fma2(sv.y, wn.y, an[r]);
                }
            }
            const float vw_r = s_vwih[j], vw_z = s_vwih[j + 128], vw_n = s_vwih[j + 256];
            const float bi_r = bih[j], bi_z = bih[j + 128], bi_n = bih[j + 256];
            const float bh_r = bhh[j], bh_z = bhh[j + 128], bh_n = bhh[j + 256];
            float nv[4];
            #pragma unroll
            for (int r = 0; r < 4; r++) {
                const int n = 4 * g + r;
                const float a = s_attn[n];
                const float hr = sum2(ar[r]) + bh_r;
                const float hz = sum2(az[r]) + bh_z;
                const float hn = sum2(an[r]) + bh_n;
                const float rr = sigm(a * vw_r + bi_r + hr);
                const float zz = sigm(a * vw_z + bi_z + hz);
                const float nn = tanha(a * vw_n + bi_n + rr * hn);
                const float h = s_slots[n * DD + j];
                nv[r] = (1.f - zz) * nn + zz * h;
            }
            __syncthreads();
            #pragma unroll
            for (int r = 0; r < 4; r++) s_slots[(4 * g + r) * DD + j] = nv[r];
        }
        __syncthreads();

        // (f) mlp-LN -> s_ln (warp per row)
        {
            const float* src = &s_slots[warp * DD];
            float x0 = src[lane], x1 = src[lane + 32], x2 = src[lane + 64], x3 = src[lane + 96];
            float s = x0 + x1 + x2 + x3;
            float q = x0 * x0 + x1 * x1 + x2 * x2 + x3 * x3;
            #pragma unroll
            for (int off = 16; off > 0; off >>= 1) {
                s += __shfl_down_sync(0xffffffffu, s, off);
                q += __shfl_down_sync(0xffffffffu, q, off);
            }
            s = __shfl_sync(0xffffffffu, s, 0);
            q = __shfl_sync(0xffffffffu, q, 0);
            const float mu = s * (1.f / 128.f);
            const float rstd = rsqrtf(q * (1.f / 128.f) - mu * mu + 1e-5f);
            float* dst = &s_ln[warp * DD];
            dst[lane]      = (x0 - mu) * rstd * s_lnp[256 + lane]      + s_lnp[384 + lane];
            dst[lane + 32] = (x1 - mu) * rstd * s_lnp[288 + lane]      + s_lnp[416 + lane];
            dst[lane + 64] = (x2 - mu) * rstd * s_lnp[320 + lane]      + s_lnp[448 + lane];
            dst[lane + 96] = (x3 - mu) * rstd * s_lnp[352 + lane]      + s_lnp[480 + lane];
        }
        __syncthreads();

        // (g) h1 = relu(ln@W1 + b1)
        {
            u64 acc[4] = {0, 0, 0, 0};
            for (int d4 = 0; d4 < 32; d4++) {
                const ulonglong2 w = pmW1[d4 * DD + j];
                #pragma unroll
                for (int r = 0; r < 4; r++) {
                    const ulonglong2 sv = *(const ulonglong2*)&s_ln[(4 * g + r) * DD + 4 * d4];
                    acc[r] = fma2(sv.x, w.x, acc[r]);
                    acc[r] = fma2(sv.y, w.y, acc[r]);
                }
            }
            const float b = mb1[j];
            #pragma unroll
            for (int r = 0; r < 4; r++)
                s_h1[(4 * g + r) * DD + j] = fmaxf(sum2(acc[r]) + b, 0.f);
        }
        __syncthreads();
        // (h) slots += h1@W2 + b2
        {
            u64 acc[4] = {0, 0, 0, 0};
            for (int d4 = 0; d4 < 32; d4++) {
                const ulonglong2 w = pmW2[d4 * DD + j];
                #pragma unroll
                for (int r = 0; r < 4; r++) {
                    const ulonglong2 sv = *(const ulonglong2*)&s_h1[(4 * g + r) * DD + 4 * d4];
                    acc[r] = fma2(sv.x, w.x, acc[r]);
                    acc[r] = fma2(sv.y, w.y, acc[r]);
                }
            }
            const float b = mb2[j];
            #pragma unroll
            for (int r = 0; r < 4; r++)
                s_slots[(4 * g + r) * DD + j] += sum2(acc[r]) + b;
        }
        __syncthreads();
    }

    // final F.normalize — warp per row
    norm_store128(&s_slots[warp * DD], out + e * (NS * DD) + warp * DD, lane);
}

// ---------------------------------------------------------------------------
// Kernel 3: persistent temporal blend. One CTA per batch b, loops t=1..63.
// ---------------------------------------------------------------------------
__global__ __launch_bounds__(512) void temporal_kernel(float* __restrict__ out)
{
    __shared__ __align__(16) float s_prev[NS * DD];
    const int tid = threadIdx.x;
    const int j = tid & 127;
    const int g = tid >> 7;
    const long b = blockIdx.x;
    float* base = out + b * 64 * (NS * DD);

    for (int i = tid; i < NS * DD; i += 512) s_prev[i] = base[i];
    __syncthreads();

    for (int t = 1; t < 64; t++) {
        float* cur = base + t * (NS * DD);
        float c[4];
        #pragma unroll
        for (int r = 0; r < 4; r++) c[r] = cur[(g * 4 + r) * DD + j];

        u64 acc[4] = {0, 0, 0, 0};
        for (int d4 = 0; d4 < 32; d4++) {
            const ulonglong2 w = pWt[d4 * DD + j];
            #pragma unroll
            for (int r = 0; r < 4; r++) {
                const ulonglong2 s = *(const ulonglong2*)&s_prev[(g * 4 + r) * DD + 4 * d4];
                acc[r] = fma2(s.x, w.x, acc[r]);
                acc[r] = fma2(s.y, w.y, acc[r]);
            }
        }
        __syncthreads();
        #pragma unroll
        for (int r = 0; r < 4; r++) {
            const float v = 0.7f * c[r] + 0.3f * tanha(sum2(acc[r]));
            cur[(g * 4 + r) * DD + j] = v;
            s_prev[(g * 4 + r) * DD + j] = v;
        }
        __syncthreads();
    }
}

// ---------------------------------------------------------------------------
extern "C" void kernel_launch(void* const* d_in, const int* in_sizes, int n_in,
                              void* d_out, int out_size)
{
    const float* obs    = (const float*)d_in[0];
    const float* eW1    = (const float*)d_in[1];
    const float* eb1    = (const float*)d_in[2];
    const float* eW2    = (const float*)d_in[3];
    const float* eb2    = (const float*)d_in[4];
    const float* skipW  = (const float*)d_in[5];
    const float* smu    = (const float*)d_in[6];
    const float* Wk     = (const float*)d_in[7];
    const float* Wv     = (const float*)d_in[8];
    const float* Wq     = (const float*)d_in[9];
    const float* gWih   = (const float*)d_in[10];
    const float* gWhh   = (const float*)d_in[11];
    const float* gbih   = (const float*)d_in[12];
    const float* gbhh   = (const float*)d_in[13];
    const float* mW1    = (const float*)d_in[14];
    const float* mb1    = (const float*)d_in[15];
    const float* mW2    = (const float*)d_in[16];
    const float* mb2    = (const float*)d_in[17];
    const float* lin_g  = (const float*)d_in[18];
    const float* lin_b  = (const float*)d_in[19];
    const float* lsl_g  = (const float*)d_in[20];
    const float* lsl_b  = (const float*)d_in[21];
    const float* lml_g  = (const float*)d_in[22];
    const float* lml_b  = (const float*)d_in[23];
    const float* Wt     = (const float*)d_in[24];
    float* out = (float*)d_out;

    pack_all<<<(106496 + 255) / 256, 256>>>(eW1, eW2, skipW, Wk, Wv, Wq,
                                            gWih, gWhh, mW1, mW2, Wt);

    enc_kernel<<<BT / 8, 256>>>(obs, eb1, eb2);

    slot_kernel<<<BT, 512>>>(smu, gbih, gbhh, mb1, mb2,
                             lin_g, lin_b, lsl_g, lsl_b, lml_g, lml_b, out);

    temporal_kernel<<<256, 512>>>(out);
}